// round 6
// baseline (speedup 1.0000x reference)
#include <cuda_runtime.h>
#include <math.h>

// ---------------------------------------------------------------------------
// GraphAttention (e3nn-style) fused kernel, fp32 baseline.
// Inputs (metadata order):
//  0 node_ft      [N,40]  f32
//  1 edge_index   [2,E]   int32 (JAX silently demotes int64 -> int32)
//  2 edge_sh      [E,4]   f32
//  3 edge_scalars [E,16]  f32
//  4 w_q_s  [16,8]   5 w_q_v [8,4]
//  6 fck_w1 [16,32]  7 fck_w2 [32,320]
//  8 fcv_w1 [16,32]  9 fcv_w2 [32,640]
// 10 wdot_s [8,8]   11 wdot_v [4,4]
// Output: [N,40] f32
// ---------------------------------------------------------------------------

#define M0 16
#define M1 8
#define Q0 8
#define Q1 4
#define O0 16
#define O1 8
#define HID 32
#define EB 16
#define TPK 320
#define TPV 640
#define NODE_DIM 40
#define OUT_DIM 40

#define N_MAX 20000
#define E_MAX 250000

// scratch (allocation-free rule: device globals)
__device__ float g_qts[N_MAX * Q0];       // folded q-tilde scalar
__device__ float g_qtv[N_MAX * Q1 * 3];   // folded q-tilde vector
__device__ float g_ex[E_MAX];             // exp(dot) per edge
__device__ float g_z[N_MAX];              // softmax denominator per node

// constants
#define INV_SQRT3 0.57735026918962576f
#define INV_SQRT2 0.70710678118654752f
#define INV_SQRT24 0.20412414523193151f
#define INV_SQRT32 0.17677669529663687f
#define INV_SQRT8 0.35355339059327373f
#define CS_FOLD 0.022821773229381923f     // 1/sqrt(24*80)
#define CV_FOLD 0.011410886614690962f     // 1/sqrt(32*3*80)

// Accumulate effective weights weff[o] = sum_h hk[h] * W2[h, base + o]
// ROW4 = row stride of W2 in float4 units; NW4 = number of float4 per i-slice.
template<int ROW4, int NW4>
__device__ __forceinline__ void weff_acc(const float* __restrict__ base,
                                         const float* __restrict__ hk,
                                         float* __restrict__ w)
{
#pragma unroll
    for (int k = 0; k < NW4 * 4; k++) w[k] = 0.f;
    const float4* b = (const float4*)base;
#pragma unroll
    for (int h = 0; h < HID; h++) {
        float c = hk[h];
#pragma unroll
        for (int j = 0; j < NW4; j++) {
            float4 a = b[h * ROW4 + j];
            w[j * 4 + 0] += c * a.x;
            w[j * 4 + 1] += c * a.y;
            w[j * 4 + 2] += c * a.z;
            w[j * 4 + 3] += c * a.w;
        }
    }
}

template<int O>
__device__ __forceinline__ void vapply(const float* __restrict__ w,
                                       float t0, float t1, float t2,
                                       float* __restrict__ acc)
{
#pragma unroll
    for (int o = 0; o < O; o++) {
        acc[o * 3 + 0] += w[o] * t0;
        acc[o * 3 + 1] += w[o] * t1;
        acc[o * 3 + 2] += w[o] * t2;
    }
}

// ---------------------------------------------------------------------------
// Kernel 1: per-node q, fold wdot + all norms into q-tilde; zero z and out.
// ---------------------------------------------------------------------------
__global__ void q_kernel(const float* __restrict__ node_ft,
                         const float* __restrict__ wqs,
                         const float* __restrict__ wqv,
                         const float* __restrict__ wds,
                         const float* __restrict__ wdv,
                         float* __restrict__ out, int N)
{
    int n = blockIdx.x * blockDim.x + threadIdx.x;
    if (n >= N) return;
    const float* x = node_ft + (size_t)n * NODE_DIM;

    float xs[M0];
#pragma unroll
    for (int i = 0; i < M0; i++) xs[i] = x[i];
    float xv[M1][3];
#pragma unroll
    for (int i = 0; i < M1; i++)
#pragma unroll
        for (int c = 0; c < 3; c++) xv[i][c] = x[M0 + i * 3 + c];

    float qs[Q0];
#pragma unroll
    for (int o = 0; o < Q0; o++) {
        float t = 0.f;
#pragma unroll
        for (int i = 0; i < M0; i++) t += xs[i] * wqs[i * Q0 + o];
        qs[o] = t * 0.25f;  // 1/sqrt(16)
    }
    float qv[Q1][3];
#pragma unroll
    for (int o = 0; o < Q1; o++)
#pragma unroll
        for (int c = 0; c < 3; c++) {
            float t = 0.f;
#pragma unroll
            for (int i = 0; i < M1; i++) t += xv[i][c] * wqv[i * Q1 + o];
            qv[o][c] = t * INV_SQRT8;
        }

#pragma unroll
    for (int j = 0; j < Q0; j++) {
        float t = 0.f;
#pragma unroll
        for (int i = 0; i < Q0; i++) t += qs[i] * wds[i * Q0 + j];
        g_qts[n * Q0 + j] = t * CS_FOLD;
    }
#pragma unroll
    for (int j = 0; j < Q1; j++)
#pragma unroll
        for (int c = 0; c < 3; c++) {
            float t = 0.f;
#pragma unroll
            for (int i = 0; i < Q1; i++) t += qv[i][c] * wdv[i * Q1 + j];
            g_qtv[n * 12 + j * 3 + c] = t * CV_FOLD;
        }

    g_z[n] = 0.f;
#pragma unroll
    for (int k = 0; k < OUT_DIM; k++) out[(size_t)n * OUT_DIM + k] = 0.f;
}

// ---------------------------------------------------------------------------
// Kernel 2 (pass 1): per-edge K tensor product + dot + exp + z accumulation.
// ---------------------------------------------------------------------------
__global__ void __launch_bounds__(256) pass1_kernel(
    const float* __restrict__ node_ft,
    const int* __restrict__ eidx,
    const float* __restrict__ edge_sh,
    const float* __restrict__ edge_sc,
    const float* __restrict__ W1g,
    const float* __restrict__ W2g,
    int E)
{
    extern __shared__ float sm[];
    float* sW1 = sm;               // [16*32]
    float* sW2 = sm + EB * HID;    // [32*320]
    for (int i = threadIdx.x; i < EB * HID; i += blockDim.x) sW1[i] = W1g[i];
    for (int i = threadIdx.x; i < HID * TPK; i += blockDim.x) sW2[i] = W2g[i];
    __syncthreads();

    int e = blockIdx.x * blockDim.x + threadIdx.x;
    if (e >= E) return;

    // hidden activations (fc layer-1 norm 1/4 folded; layer-2 norm 1/sqrt(32) folded into hk)
    float sv[EB];
    {
        const float4* sp = (const float4*)(edge_sc + (size_t)e * EB);
#pragma unroll
        for (int i = 0; i < EB / 4; i++) {
            float4 v = sp[i];
            sv[i * 4 + 0] = v.x; sv[i * 4 + 1] = v.y;
            sv[i * 4 + 2] = v.z; sv[i * 4 + 3] = v.w;
        }
    }
    float hk[HID];
#pragma unroll
    for (int h = 0; h < HID; h++) {
        float t = 0.f;
#pragma unroll
        for (int i = 0; i < EB; i++) t += sv[i] * sW1[i * HID + h];
        t *= 0.25f;
        hk[h] = (t / (1.0f + __expf(-t))) * INV_SQRT32;   // silu * layer2 norm
    }

    int snd = eidx[e];
    const float* x = node_ft + (size_t)snd * NODE_DIM;
    float xs[M0];
    float xv[M1][3];
    {
        const float4* xp = (const float4*)x;
#pragma unroll
        for (int i = 0; i < 4; i++) {
            float4 v = xp[i];
            xs[i * 4 + 0] = v.x; xs[i * 4 + 1] = v.y;
            xs[i * 4 + 2] = v.z; xs[i * 4 + 3] = v.w;
        }
        float tmp[24];
#pragma unroll
        for (int i = 0; i < 6; i++) {
            float4 v = xp[4 + i];
            tmp[i * 4 + 0] = v.x; tmp[i * 4 + 1] = v.y;
            tmp[i * 4 + 2] = v.z; tmp[i * 4 + 3] = v.w;
        }
#pragma unroll
        for (int i = 0; i < M1; i++)
#pragma unroll
            for (int c = 0; c < 3; c++) xv[i][c] = tmp[i * 3 + c];
    }
    float4 sh = ((const float4*)edge_sh)[e];
    float sh0 = sh.x, shx = sh.y, shy = sh.z, shz = sh.w;

    float pvv[M1];
#pragma unroll
    for (int i = 0; i < M1; i++)
        pvv[i] = (xv[i][0] * shx + xv[i][1] * shy + xv[i][2] * shz) * INV_SQRT3;

    float ks[Q0] = {0, 0, 0, 0, 0, 0, 0, 0};
    float kv[Q1 * 3] = {0, 0, 0, 0, 0, 0, 0, 0, 0, 0, 0, 0};

    // path1: ss -> scalar, weights [16,8] at offset 0
#pragma unroll 1
    for (int i = 0; i < M0; i++) {
        float w[8];
        weff_acc<TPK / 4, 2>(sW2 + i * Q0, hk, w);
        float p = xs[i] * sh0;
#pragma unroll
        for (int o = 0; o < Q0; o++) ks[o] += p * w[o];
    }
    // path2: vv -> scalar, [8,8] at 128
#pragma unroll 1
    for (int i = 0; i < M1; i++) {
        float w[8];
        weff_acc<TPK / 4, 2>(sW2 + 128 + i * Q0, hk, w);
        float p = pvv[i];
#pragma unroll
        for (int o = 0; o < Q0; o++) ks[o] += p * w[o];
    }
    // path3: sv -> vector, [16,4] at 192
#pragma unroll 1
    for (int i = 0; i < M0; i++) {
        float w[4];
        weff_acc<TPK / 4, 1>(sW2 + 192 + i * Q1, hk, w);
        float p = xs[i];
        vapply<Q1>(w, p * shx, p * shy, p * shz, kv);
    }
    // path4: vs -> vector, [8,4] at 256
#pragma unroll 1
    for (int i = 0; i < M1; i++) {
        float w[4];
        weff_acc<TPK / 4, 1>(sW2 + 256 + i * Q1, hk, w);
        vapply<Q1>(w, xv[i][0] * sh0, xv[i][1] * sh0, xv[i][2] * sh0, kv);
    }
    // path5: cross -> vector, [8,4] at 288
#pragma unroll 1
    for (int i = 0; i < M1; i++) {
        float w[4];
        weff_acc<TPK / 4, 1>(sW2 + 288 + i * Q1, hk, w);
        float cx = (xv[i][1] * shz - xv[i][2] * shy) * INV_SQRT2;
        float cy = (xv[i][2] * shx - xv[i][0] * shz) * INV_SQRT2;
        float cz = (xv[i][0] * shy - xv[i][1] * shx) * INV_SQRT2;
        vapply<Q1>(w, cx, cy, cz, kv);
    }

    int rcv = eidx[E + e];
    const float* qts = g_qts + (size_t)rcv * Q0;
    const float* qtv = g_qtv + (size_t)rcv * 12;
    float dot = 0.f;
#pragma unroll
    for (int o = 0; o < Q0; o++) dot += qts[o] * ks[o];
#pragma unroll
    for (int j = 0; j < 12; j++) dot += qtv[j] * kv[j];

    float ex = expf(dot);
    g_ex[e] = ex;
    atomicAdd(&g_z[rcv], ex);
}

// ---------------------------------------------------------------------------
// Kernel 3 (pass 2): per-edge V tensor product, softmax weight, scatter-add.
// ---------------------------------------------------------------------------
__global__ void __launch_bounds__(256) pass2_kernel(
    const float* __restrict__ node_ft,
    const int* __restrict__ eidx,
    const float* __restrict__ edge_sh,
    const float* __restrict__ edge_sc,
    const float* __restrict__ W1g,
    const float* __restrict__ W2g,
    float* __restrict__ out,
    int E)
{
    extern __shared__ float sm[];
    float* sW1 = sm;               // [16*32]
    float* sW2 = sm + EB * HID;    // [32*640]
    for (int i = threadIdx.x; i < EB * HID; i += blockDim.x) sW1[i] = W1g[i];
    for (int i = threadIdx.x; i < HID * TPV; i += blockDim.x) sW2[i] = W2g[i];
    __syncthreads();

    int e = blockIdx.x * blockDim.x + threadIdx.x;
    if (e >= E) return;

    float sv[EB];
    {
        const float4* sp = (const float4*)(edge_sc + (size_t)e * EB);
#pragma unroll
        for (int i = 0; i < EB / 4; i++) {
            float4 v = sp[i];
            sv[i * 4 + 0] = v.x; sv[i * 4 + 1] = v.y;
            sv[i * 4 + 2] = v.z; sv[i * 4 + 3] = v.w;
        }
    }
    float hk[HID];
#pragma unroll
    for (int h = 0; h < HID; h++) {
        float t = 0.f;
#pragma unroll
        for (int i = 0; i < EB; i++) t += sv[i] * sW1[i * HID + h];
        t *= 0.25f;
        hk[h] = (t / (1.0f + __expf(-t))) * INV_SQRT32;
    }

    int snd = eidx[e];
    const float* x = node_ft + (size_t)snd * NODE_DIM;
    float xs[M0];
    float xv[M1][3];
    {
        const float4* xp = (const float4*)x;
#pragma unroll
        for (int i = 0; i < 4; i++) {
            float4 v = xp[i];
            xs[i * 4 + 0] = v.x; xs[i * 4 + 1] = v.y;
            xs[i * 4 + 2] = v.z; xs[i * 4 + 3] = v.w;
        }
        float tmp[24];
#pragma unroll
        for (int i = 0; i < 6; i++) {
            float4 v = xp[4 + i];
            tmp[i * 4 + 0] = v.x; tmp[i * 4 + 1] = v.y;
            tmp[i * 4 + 2] = v.z; tmp[i * 4 + 3] = v.w;
        }
#pragma unroll
        for (int i = 0; i < M1; i++)
#pragma unroll
            for (int c = 0; c < 3; c++) xv[i][c] = tmp[i * 3 + c];
    }
    float4 sh = ((const float4*)edge_sh)[e];
    float sh0 = sh.x, shx = sh.y, shy = sh.z, shz = sh.w;

    float pvv[M1];
#pragma unroll
    for (int i = 0; i < M1; i++)
        pvv[i] = (xv[i][0] * shx + xv[i][1] * shy + xv[i][2] * shz) * INV_SQRT3;

    float vs[O0];
#pragma unroll
    for (int o = 0; o < O0; o++) vs[o] = 0.f;
    float vvv[O1 * 3];
#pragma unroll
    for (int j = 0; j < O1 * 3; j++) vvv[j] = 0.f;

    // path1: ss -> scalar, [16,16] at 0
#pragma unroll 1
    for (int i = 0; i < M0; i++) {
        float w[16];
        weff_acc<TPV / 4, 4>(sW2 + i * O0, hk, w);
        float p = xs[i] * sh0;
#pragma unroll
        for (int o = 0; o < O0; o++) vs[o] += p * w[o];
    }
    // path2: vv -> scalar, [8,16] at 256
#pragma unroll 1
    for (int i = 0; i < M1; i++) {
        float w[16];
        weff_acc<TPV / 4, 4>(sW2 + 256 + i * O0, hk, w);
        float p = pvv[i];
#pragma unroll
        for (int o = 0; o < O0; o++) vs[o] += p * w[o];
    }
    // path3: sv -> vector, [16,8] at 384
#pragma unroll 1
    for (int i = 0; i < M0; i++) {
        float w[8];
        weff_acc<TPV / 4, 2>(sW2 + 384 + i * O1, hk, w);
        float p = xs[i];
        vapply<O1>(w, p * shx, p * shy, p * shz, vvv);
    }
    // path4: vs -> vector, [8,8] at 512
#pragma unroll 1
    for (int i = 0; i < M1; i++) {
        float w[8];
        weff_acc<TPV / 4, 2>(sW2 + 512 + i * O1, hk, w);
        vapply<O1>(w, xv[i][0] * sh0, xv[i][1] * sh0, xv[i][2] * sh0, vvv);
    }
    // path5: cross -> vector, [8,8] at 576
#pragma unroll 1
    for (int i = 0; i < M1; i++) {
        float w[8];
        weff_acc<TPV / 4, 2>(sW2 + 576 + i * O1, hk, w);
        float cx = (xv[i][1] * shz - xv[i][2] * shy) * INV_SQRT2;
        float cy = (xv[i][2] * shx - xv[i][0] * shz) * INV_SQRT2;
        float cz = (xv[i][0] * shy - xv[i][1] * shx) * INV_SQRT2;
        vapply<O1>(w, cx, cy, cz, vvv);
    }

    int rcv = eidx[E + e];
    float a = sqrtf(g_ex[e] / g_z[rcv]);
    float cs = a * INV_SQRT24;
    float cv = a * INV_SQRT32;
    float* op = out + (size_t)rcv * OUT_DIM;
#pragma unroll
    for (int o = 0; o < O0; o++) atomicAdd(op + o, cs * vs[o]);
#pragma unroll
    for (int j = 0; j < O1 * 3; j++) atomicAdd(op + O0 + j, cv * vvv[j]);
}

// ---------------------------------------------------------------------------
extern "C" void kernel_launch(void* const* d_in, const int* in_sizes, int n_in,
                              void* d_out, int out_size)
{
    const float* node_ft     = (const float*)d_in[0];
    const int* eidx          = (const int*)d_in[1];
    const float* edge_sh     = (const float*)d_in[2];
    const float* edge_sc     = (const float*)d_in[3];
    const float* wqs         = (const float*)d_in[4];
    const float* wqv         = (const float*)d_in[5];
    const float* fck_w1      = (const float*)d_in[6];
    const float* fck_w2      = (const float*)d_in[7];
    const float* fcv_w1      = (const float*)d_in[8];
    const float* fcv_w2      = (const float*)d_in[9];
    const float* wds         = (const float*)d_in[10];
    const float* wdv         = (const float*)d_in[11];
    float* out = (float*)d_out;

    int N = in_sizes[0] / NODE_DIM;
    int E = in_sizes[1] / 2;

    size_t smem1 = (size_t)(EB * HID + HID * TPK) * sizeof(float);  // 43008
    size_t smem2 = (size_t)(EB * HID + HID * TPV) * sizeof(float);  // 83968
    cudaFuncSetAttribute(pass1_kernel, cudaFuncAttributeMaxDynamicSharedMemorySize, (int)smem1);
    cudaFuncSetAttribute(pass2_kernel, cudaFuncAttributeMaxDynamicSharedMemorySize, (int)smem2);

    q_kernel<<<(N + 255) / 256, 256>>>(node_ft, wqs, wqv, wds, wdv, out, N);
    pass1_kernel<<<(E + 255) / 256, 256, smem1>>>(node_ft, eidx, edge_sh, edge_sc,
                                                  fck_w1, fck_w2, E);
    pass2_kernel<<<(E + 255) / 256, 256, smem2>>>(node_ft, eidx, edge_sh, edge_sc,
                                                  fcv_w1, fcv_w2, out, E);
}